// round 16
// baseline (speedup 1.0000x reference)
#include <cuda_runtime.h>
#include <math.h>

#define BB   128
#define LS   5000
#define DM   8
#define DI   16
#define DS   16
#define NL   4
#define HIDC 64
#define NC   230

// ---------------- scratch (no cudaMalloc allowed) ----------------
__device__ float  g_f [BB*LS*DM];      // residual stream (B,L,8)
__device__ float  g_z [BB*LS*DI];      // gate pre-act
__device__ float  g_u [BB*LS*DI];      // silu(conv(xc))
__device__ float2 g_dd[BB*LS*DI];      // (delta, delta*u)
__device__ float2 g_bc[BB*LS*DS];      // (B, C)
__device__ float  g_y [BB*LS*DI];      // scan output (without D*u)
__device__ float  g_h1[BB*HIDC*LS];    // conv1 output (B,64,L)
__device__ float  g_r [BB*HIDC*LS];    // conv2 output
__device__ float  g_pool[BB*HIDC];     // pooled sums

// ---------------- embed ----------------
__global__ void k_embed(const float* __restrict__ x, const int* __restrict__ idx,
                        const float* __restrict__ emb) {
    int id = blockIdx.x * blockDim.x + threadIdx.x;
    if (id >= BB * LS) return;
    int l = id % LS;
    float xv = x[id];
    const float* e = emb + (size_t)idx[l] * DM;
    float* o = g_f + (size_t)id * DM;
#pragma unroll
    for (int d = 0; d < DM; d++) o[d] = e[d] * xv;
}

__global__ void k_zero() {
    int i = blockIdx.x * blockDim.x + threadIdx.x;
    if (i < BB * HIDC) g_pool[i] = 0.f;
}

// ---------------- phase A: norm + in_proj + conv + silu + x_proj + dt ----------------
#define LTA 128
__global__ void k_layerA(const float* __restrict__ norm_w, const float* __restrict__ inw,
                         const float* __restrict__ cw, const float* __restrict__ cb,
                         const float* __restrict__ xw, const float* __restrict__ dtw,
                         const float* __restrict__ dtb) {
    __shared__ float s_norm[DM];
    __shared__ float s_inw[32 * DM];
    __shared__ float s_cw[DI * 3], s_cb[DI];
    __shared__ float s_xw[33 * DI];
    __shared__ float s_dtw[DI], s_dtb[DI];
    __shared__ float s_xc[LTA + 2][DI + 1];   // +1 pad: conflict-free

    int tid = threadIdx.x;
    if (tid < DM) s_norm[tid] = norm_w[tid];
    for (int i = tid; i < 32 * DM; i += LTA) s_inw[i] = inw[i];
    for (int i = tid; i < DI * 3; i += LTA) s_cw[i] = cw[i];
    if (tid < DI) { s_cb[tid] = cb[tid]; s_dtw[tid] = dtw[tid]; s_dtb[tid] = dtb[tid]; }
    for (int i = tid; i < 33 * DI; i += LTA) s_xw[i] = xw[i];
    __syncthreads();

    int b = blockIdx.y;
    int l0 = blockIdx.x * LTA;
    int pos = l0 + tid;
    bool valid = pos < LS;

    float xn[DM];
    if (valid) {
        const float* fp = g_f + ((size_t)b * LS + pos) * DM;
        float s = 0.f;
#pragma unroll
        for (int d = 0; d < DM; d++) { float v = fp[d]; xn[d] = v; s += v * v; }
        float inv = rsqrtf(s * (1.0f / DM) + 1e-5f);
#pragma unroll
        for (int d = 0; d < DM; d++) xn[d] *= inv * s_norm[d];
#pragma unroll
        for (int c = 0; c < DI; c++) {
            float a = 0.f;
#pragma unroll
            for (int d = 0; d < DM; d++) a += s_inw[c * DM + d] * xn[d];
            s_xc[tid + 2][c] = a;
        }
        float* zp = g_z + ((size_t)b * LS + pos) * DI;
#pragma unroll
        for (int c = 0; c < DI; c++) {
            float a = 0.f;
#pragma unroll
            for (int d = 0; d < DM; d++) a += s_inw[(DI + c) * DM + d] * xn[d];
            zp[c] = a;
        }
    }
    // halo: recompute xc_pre for l0-2, l0-1 (zeros if < 0 => causal zero pad)
    if (tid < 2) {
        int hp = l0 - 2 + tid;
        float acc[DI];
#pragma unroll
        for (int c = 0; c < DI; c++) acc[c] = 0.f;
        if (hp >= 0) {
            const float* fp = g_f + ((size_t)b * LS + hp) * DM;
            float xh[DM]; float s = 0.f;
#pragma unroll
            for (int d = 0; d < DM; d++) { float v = fp[d]; xh[d] = v; s += v * v; }
            float inv = rsqrtf(s * (1.0f / DM) + 1e-5f);
#pragma unroll
            for (int d = 0; d < DM; d++) xh[d] *= inv * s_norm[d];
#pragma unroll
            for (int c = 0; c < DI; c++) {
                float a = 0.f;
#pragma unroll
                for (int d = 0; d < DM; d++) a += s_inw[c * DM + d] * xh[d];
                acc[c] = a;
            }
        }
#pragma unroll
        for (int c = 0; c < DI; c++) s_xc[tid][c] = acc[c];
    }
    __syncthreads();
    if (!valid) return;

    float uu[DI];
#pragma unroll
    for (int c = 0; c < DI; c++) {
        float a = s_cb[c] + s_cw[c * 3 + 0] * s_xc[tid][c]
                          + s_cw[c * 3 + 1] * s_xc[tid + 1][c]
                          + s_cw[c * 3 + 2] * s_xc[tid + 2][c];
        uu[c] = a / (1.f + __expf(-a));            // silu
    }
    float* up = g_u + ((size_t)b * LS + pos) * DI;
#pragma unroll
    for (int c = 0; c < DI; c++) up[c] = uu[c];

    float dr = 0.f;
#pragma unroll
    for (int c = 0; c < DI; c++) dr += s_xw[c] * uu[c];

    float2* bcp = g_bc + ((size_t)b * LS + pos) * DS;
#pragma unroll
    for (int nn = 0; nn < DS; nn++) {
        float Bv = 0.f, Cv = 0.f;
#pragma unroll
        for (int c = 0; c < DI; c++) {
            Bv += s_xw[(1 + nn) * DI + c] * uu[c];
            Cv += s_xw[(1 + DS + nn) * DI + c] * uu[c];
        }
        bcp[nn] = make_float2(Bv, Cv);
    }
    float2* ddp = g_dd + ((size_t)b * LS + pos) * DI;
#pragma unroll
    for (int e = 0; e < DI; e++) {
        float t = dr * s_dtw[e] + s_dtb[e];
        float delta = (t > 20.f) ? t : log1pf(__expf(t));   // softplus
        ddp[e] = make_float2(delta, delta * uu[e]);
    }
}

// ---------------- selective scan: 1 block / batch, thread = (e,n) ----------------
__global__ void k_scan(const float* __restrict__ A_log) {
    int b = blockIdx.x;
    int tid = threadIdx.x;
    int e = tid >> 4, n = tid & 15;
    float A = -__expf(A_log[e * DS + n]);
    const float2* pdd = g_dd + (size_t)b * LS * DI + e;
    const float2* pbc = g_bc + (size_t)b * LS * DS + n;
    float* py = g_y + (size_t)b * LS * DI + e;

    float h = 0.f;
    float2 d2 = pdd[0];
    float2 cc = pbc[0];
#pragma unroll 4
    for (int t = 0; t < LS; t++) {
        float2 d2c = d2, ccc = cc;
        if (t + 1 < LS) {                     // prefetch next step (off critical path)
            d2 = pdd[(size_t)(t + 1) * DI];
            cc = pbc[(size_t)(t + 1) * DS];
        }
        float dA = __expf(d2c.x * A);
        h = __fmaf_rn(dA, h, d2c.y * ccc.x);  // h = exp(dt*A)*h + dt*u*B
        float v = h * ccc.y;
        v += __shfl_xor_sync(0xffffffffu, v, 1);
        v += __shfl_xor_sync(0xffffffffu, v, 2);
        v += __shfl_xor_sync(0xffffffffu, v, 4);
        v += __shfl_xor_sync(0xffffffffu, v, 8);
        if (n == 0) py[(size_t)t * DI] = v;
    }
}

// ---------------- phase C: f += out_proj @ ((y + D*u)*silu(z)) ----------------
__global__ void k_mix(const float* __restrict__ ow, const float* __restrict__ Dp) {
    __shared__ float s_w[DM * DI];
    __shared__ float s_D[DI];
    int tid = threadIdx.x;
    if (tid < DM * DI) s_w[tid] = ow[tid];
    if (tid < DI) s_D[tid] = Dp[tid];
    __syncthreads();
    int id = blockIdx.x * blockDim.x + tid;
    if (id >= BB * LS) return;
    const float* yp = g_y + (size_t)id * DI;
    const float* up = g_u + (size_t)id * DI;
    const float* zp = g_z + (size_t)id * DI;
    float g[DI];
#pragma unroll
    for (int c = 0; c < DI; c++) {
        float yv = yp[c] + s_D[c] * up[c];
        float zz = zp[c];
        g[c] = yv * (zz / (1.f + __expf(-zz)));
    }
    float* fp = g_f + (size_t)id * DM;
#pragma unroll
    for (int d = 0; d < DM; d++) {
        float a = 0.f;
#pragma unroll
        for (int c = 0; c < DI; c++) a += s_w[d * DI + c] * g[c];
        fp[d] += a;
    }
}

// ---------------- conv1: 8 -> 64, k=3, pad same, relu ----------------
#define LT1 128
__global__ void k_conv1(const float* __restrict__ w, const float* __restrict__ bias) {
    __shared__ float s_in[DM][LT1 + 2];
    __shared__ float s_w[HIDC * DM * 3];
    __shared__ float s_b[HIDC];
    int tid = threadIdx.x;                    // 256
    int b = blockIdx.y;
    int l0 = blockIdx.x * LT1;
    for (int i = tid; i < HIDC * DM * 3; i += 256) s_w[i] = w[i];
    if (tid < HIDC) s_b[tid] = bias[tid];
    for (int i = tid; i < DM * (LT1 + 2); i += 256) {
        int li = i / DM, d = i % DM;
        int l = l0 - 1 + li;
        s_in[d][li] = (l >= 0 && l < LS) ? g_f[((size_t)b * LS + l) * DM + d] : 0.f;
    }
    __syncthreads();
    int c = tid & 63, pg = tid >> 6;          // 4 groups x 32 positions
    float wr[24];
#pragma unroll
    for (int j = 0; j < 24; j++) wr[j] = s_w[c * 24 + j];
    float bb = s_b[c];
    int pbase = pg * 32;
    for (int j0 = 0; j0 < 32; j0 += 4) {
        int p = pbase + j0;
        float a0 = bb, a1 = bb, a2 = bb, a3 = bb;
#pragma unroll
        for (int d = 0; d < DM; d++) {
            float x0 = s_in[d][p + 0], x1 = s_in[d][p + 1], x2 = s_in[d][p + 2];
            float x3 = s_in[d][p + 3], x4 = s_in[d][p + 4], x5 = s_in[d][p + 5];
            float w0 = wr[d * 3 + 0], w1 = wr[d * 3 + 1], w2 = wr[d * 3 + 2];
            a0 += w0 * x0 + w1 * x1 + w2 * x2;
            a1 += w0 * x1 + w1 * x2 + w2 * x3;
            a2 += w0 * x2 + w1 * x3 + w2 * x4;
            a3 += w0 * x3 + w1 * x4 + w2 * x5;
        }
        int l = l0 + p;
        float* op = g_h1 + ((size_t)b * HIDC + c) * LS + l;
        if (l + 3 < LS) {
            *(float4*)op = make_float4(fmaxf(a0, 0.f), fmaxf(a1, 0.f),
                                       fmaxf(a2, 0.f), fmaxf(a3, 0.f));
        } else {
            if (l + 0 < LS) op[0] = fmaxf(a0, 0.f);
            if (l + 1 < LS) op[1] = fmaxf(a1, 0.f);
            if (l + 2 < LS) op[2] = fmaxf(a2, 0.f);
            if (l + 3 < LS) op[3] = fmaxf(a3, 0.f);
        }
    }
}

// ---------------- conv2: 64 -> 64, k=3, relu ----------------
#define LT2 64
__global__ void k_conv2(const float* __restrict__ w, const float* __restrict__ bias) {
    __shared__ float s_in[HIDC][LT2 + 2];     // 16.9 KB
    __shared__ float s_w[192 * 32];           // transposed: [(ci*3+k)*32 + c_local]
    __shared__ float s_b[32];
    int tid = threadIdx.x;                    // 256
    int b = blockIdx.y;
    int l0 = blockIdx.x * LT2;
    int ch = blockIdx.z;                      // c_out half
    for (int i = tid; i < HIDC * (LT2 + 2); i += 256) {
        int ci = i / (LT2 + 2), li = i % (LT2 + 2);
        int l = l0 - 1 + li;
        s_in[ci][li] = (l >= 0 && l < LS) ? g_h1[((size_t)b * HIDC + ci) * LS + l] : 0.f;
    }
    for (int i = tid; i < 32 * 192; i += 256) {
        int cl = i / 192, rem = i % 192;
        s_w[rem * 32 + cl] = w[(size_t)(ch * 32 + cl) * 192 + rem];
    }
    if (tid < 32) s_b[tid] = bias[ch * 32 + tid];
    __syncthreads();

    int c = tid & 31, pg = tid >> 5;          // 8 groups x 8 positions
    int p0 = pg * 8;
    float acc[8];
    float bb = s_b[c];
#pragma unroll
    for (int j = 0; j < 8; j++) acc[j] = bb;
    for (int ci = 0; ci < HIDC; ci++) {
        float w0 = s_w[(ci * 3 + 0) * 32 + c];
        float w1 = s_w[(ci * 3 + 1) * 32 + c];
        float w2 = s_w[(ci * 3 + 2) * 32 + c];
        float x[10];
#pragma unroll
        for (int j = 0; j < 10; j++) x[j] = s_in[ci][p0 + j];
#pragma unroll
        for (int j = 0; j < 8; j++) acc[j] += w0 * x[j] + w1 * x[j + 1] + w2 * x[j + 2];
    }
    int cg = ch * 32 + c;
    int l = l0 + p0;
    float* op = g_r + ((size_t)b * HIDC + cg) * LS + l;
#pragma unroll
    for (int j = 0; j < 8; j += 4) {
        if (l + j + 3 < LS) {
            *(float4*)(op + j) = make_float4(fmaxf(acc[j], 0.f), fmaxf(acc[j + 1], 0.f),
                                             fmaxf(acc[j + 2], 0.f), fmaxf(acc[j + 3], 0.f));
        } else {
#pragma unroll
            for (int jj = 0; jj < 4; jj++)
                if (l + j + jj < LS) op[j + jj] = fmaxf(acc[j + jj], 0.f);
        }
    }
}

// ---------------- conv3 + residual + relu + mean-pool partial ----------------
#define LT3 48
__global__ void k_conv3(const float* __restrict__ w, const float* __restrict__ bias) {
    __shared__ float s_in[HIDC][LT3 + 2];     // 12.8 KB (r tile)
    __shared__ float s_w[192 * 32];           // 24.6 KB
    __shared__ float s_h[32][LT3 + 1];        // 6.3 KB (h1 tile, padded)
    __shared__ float s_b[32];
    __shared__ float s_red[8][33];
    int tid = threadIdx.x;                    // 256
    int b = blockIdx.y;
    int l0 = blockIdx.x * LT3;
    int ch = blockIdx.z;
    for (int i = tid; i < HIDC * (LT3 + 2); i += 256) {
        int ci = i / (LT3 + 2), li = i % (LT3 + 2);
        int l = l0 - 1 + li;
        s_in[ci][li] = (l >= 0 && l < LS) ? g_r[((size_t)b * HIDC + ci) * LS + l] : 0.f;
    }
    for (int i = tid; i < 32 * 192; i += 256) {
        int cl = i / 192, rem = i % 192;
        s_w[rem * 32 + cl] = w[(size_t)(ch * 32 + cl) * 192 + rem];
    }
    for (int i = tid; i < 32 * LT3; i += 256) {
        int cl = i / LT3, li = i % LT3;
        int l = l0 + li;
        s_h[cl][li] = (l < LS) ? g_h1[((size_t)b * HIDC + ch * 32 + cl) * LS + l] : 0.f;
    }
    if (tid < 32) s_b[tid] = bias[ch * 32 + tid];
    __syncthreads();

    int c = tid & 31, pg = tid >> 5;          // 8 groups x 6 positions
    int p0 = pg * 6;
    float acc[6];
    float bb = s_b[c];
#pragma unroll
    for (int j = 0; j < 6; j++) acc[j] = bb;
    for (int ci = 0; ci < HIDC; ci++) {
        float w0 = s_w[(ci * 3 + 0) * 32 + c];
        float w1 = s_w[(ci * 3 + 1) * 32 + c];
        float w2 = s_w[(ci * 3 + 2) * 32 + c];
        float x[8];
#pragma unroll
        for (int j = 0; j < 8; j++) x[j] = s_in[ci][p0 + j];
#pragma unroll
        for (int j = 0; j < 6; j++) acc[j] += w0 * x[j] + w1 * x[j + 1] + w2 * x[j + 2];
    }
    float psum = 0.f;
    int l = l0 + p0;
#pragma unroll
    for (int j = 0; j < 6; j++) {
        if (l + j < LS) {
            float t = acc[j] + s_h[c][p0 + j];    // h1 + conv3(r)
            psum += fmaxf(t, 0.f);
        }
    }
    s_red[pg][c] = psum;
    __syncthreads();
    if (tid < 32) {
        float s = 0.f;
#pragma unroll
        for (int g = 0; g < 8; g++) s += s_red[g][tid];
        atomicAdd(&g_pool[b * HIDC + ch * 32 + tid], s);
    }
}

// ---------------- fc ----------------
__global__ void k_fc(const float* __restrict__ fw, const float* __restrict__ fb,
                     float* __restrict__ out) {
    __shared__ float s_p[HIDC];
    int b = blockIdx.x, tid = threadIdx.x;
    if (tid < HIDC) s_p[tid] = g_pool[b * HIDC + tid] * (1.0f / LS);
    __syncthreads();
    if (tid < NC) {
        float a = fb[tid];
#pragma unroll
        for (int c = 0; c < HIDC; c++) a += fw[tid * HIDC + c] * s_p[c];
        out[b * NC + tid] = a;
    }
}

// ---------------- launch ----------------
extern "C" void kernel_launch(void* const* d_in, const int* in_sizes, int n_in,
                              void* d_out, int out_size) {
    const float* x          = (const float*)d_in[0];
    const int*   idx        = (const int*)  d_in[1];
    const float* emb        = (const float*)d_in[2];
    const float* norm_w     = (const float*)d_in[3];
    const float* in_proj_w  = (const float*)d_in[4];
    const float* conv_w     = (const float*)d_in[5];
    const float* conv_b     = (const float*)d_in[6];
    const float* x_proj_w   = (const float*)d_in[7];
    const float* dt_proj_w  = (const float*)d_in[8];
    const float* dt_proj_b  = (const float*)d_in[9];
    const float* A_log      = (const float*)d_in[10];
    const float* Dp         = (const float*)d_in[11];
    const float* out_proj_w = (const float*)d_in[12];
    const float* c1w        = (const float*)d_in[13];
    const float* c1b        = (const float*)d_in[14];
    const float* c2w        = (const float*)d_in[15];
    const float* c2b        = (const float*)d_in[16];
    const float* c3w        = (const float*)d_in[17];
    const float* c3b        = (const float*)d_in[18];
    const float* fcw        = (const float*)d_in[19];
    const float* fcb        = (const float*)d_in[20];
    float* out = (float*)d_out;

    k_embed<<<(BB * LS + 255) / 256, 256>>>(x, idx, emb);
    k_zero<<<(BB * HIDC + 255) / 256, 256>>>();

    for (int l = 0; l < NL; l++) {
        k_layerA<<<dim3((LS + LTA - 1) / LTA, BB), LTA>>>(
            norm_w + l * DM, in_proj_w + l * 32 * DM, conv_w + l * DI * 3,
            conv_b + l * DI, x_proj_w + l * 33 * DI, dt_proj_w + l * DI,
            dt_proj_b + l * DI);
        k_scan<<<BB, 256>>>(A_log + l * DI * DS);
        k_mix<<<(BB * LS + 255) / 256, 256>>>(out_proj_w + l * DM * DI, Dp + l * DI);
    }

    k_conv1<<<dim3((LS + LT1 - 1) / LT1, BB), 256>>>(c1w, c1b);
    k_conv2<<<dim3((LS + LT2 - 1) / LT2, BB, 2), 256>>>(c2w, c2b);
    k_conv3<<<dim3((LS + LT3 - 1) / LT3, BB, 2), 256>>>(c3w, c3b);
    k_fc<<<BB, 256>>>(fcw, fcb, out);
}

// round 17
// speedup vs baseline: 1.0032x; 1.0032x over previous
#include <cuda_runtime.h>
#include <math.h>

#define BB   128
#define LS   5000
#define DM   8
#define DI   16
#define DS   16
#define NL   4
#define HIDC 64
#define NC   230

// ---------------- scratch (no cudaMalloc allowed) ----------------
__device__ float  g_f [BB*LS*DM];      // residual stream (B,L,8)
__device__ float  g_z [BB*LS*DI];      // gate pre-act
__device__ float  g_u [BB*LS*DI];      // silu(conv(xc))
__device__ float2 g_dd[BB*LS*DI];      // (delta, delta*u)
__device__ float2 g_bc[BB*LS*DS];      // (B, C)
__device__ float  g_y [BB*LS*DI];      // scan output (without D*u)
__device__ float  g_h1[BB*HIDC*LS];    // conv1 output (B,64,L)
__device__ float  g_r [BB*HIDC*LS];    // conv2 output
__device__ float  g_pool[BB*HIDC];     // pooled sums

// ---------------- embed ----------------
__global__ void k_embed(const float* __restrict__ x, const int* __restrict__ idx,
                        const float* __restrict__ emb) {
    int id = blockIdx.x * blockDim.x + threadIdx.x;
    if (id >= BB * LS) return;
    int l = id % LS;
    float xv = x[id];
    const float* e = emb + (size_t)idx[l] * DM;
    float* o = g_f + (size_t)id * DM;
#pragma unroll
    for (int d = 0; d < DM; d++) o[d] = e[d] * xv;
}

__global__ void k_zero() {
    int i = blockIdx.x * blockDim.x + threadIdx.x;
    if (i < BB * HIDC) g_pool[i] = 0.f;
}

// ---------------- phase A: norm + in_proj + conv + silu + x_proj + dt ----------------
#define LTA 128
__global__ void k_layerA(const float* __restrict__ norm_w, const float* __restrict__ inw,
                         const float* __restrict__ cw, const float* __restrict__ cb,
                         const float* __restrict__ xw, const float* __restrict__ dtw,
                         const float* __restrict__ dtb) {
    __shared__ float s_norm[DM];
    __shared__ float s_inw[32 * DM];
    __shared__ float s_cw[DI * 3], s_cb[DI];
    __shared__ float s_xw[33 * DI];
    __shared__ float s_dtw[DI], s_dtb[DI];
    __shared__ float s_xc[LTA + 2][DI + 1];   // +1 pad: conflict-free

    int tid = threadIdx.x;
    if (tid < DM) s_norm[tid] = norm_w[tid];
    for (int i = tid; i < 32 * DM; i += LTA) s_inw[i] = inw[i];
    for (int i = tid; i < DI * 3; i += LTA) s_cw[i] = cw[i];
    if (tid < DI) { s_cb[tid] = cb[tid]; s_dtw[tid] = dtw[tid]; s_dtb[tid] = dtb[tid]; }
    for (int i = tid; i < 33 * DI; i += LTA) s_xw[i] = xw[i];
    __syncthreads();

    int b = blockIdx.y;
    int l0 = blockIdx.x * LTA;
    int pos = l0 + tid;
    bool valid = pos < LS;

    float xn[DM];
    if (valid) {
        const float* fp = g_f + ((size_t)b * LS + pos) * DM;
        float s = 0.f;
#pragma unroll
        for (int d = 0; d < DM; d++) { float v = fp[d]; xn[d] = v; s += v * v; }
        float inv = rsqrtf(s * (1.0f / DM) + 1e-5f);
#pragma unroll
        for (int d = 0; d < DM; d++) xn[d] *= inv * s_norm[d];
#pragma unroll
        for (int c = 0; c < DI; c++) {
            float a = 0.f;
#pragma unroll
            for (int d = 0; d < DM; d++) a += s_inw[c * DM + d] * xn[d];
            s_xc[tid + 2][c] = a;
        }
        float* zp = g_z + ((size_t)b * LS + pos) * DI;
#pragma unroll
        for (int c = 0; c < DI; c++) {
            float a = 0.f;
#pragma unroll
            for (int d = 0; d < DM; d++) a += s_inw[(DI + c) * DM + d] * xn[d];
            zp[c] = a;
        }
    }
    // halo: recompute xc_pre for l0-2, l0-1 (zeros if < 0 => causal zero pad)
    if (tid < 2) {
        int hp = l0 - 2 + tid;
        float acc[DI];
#pragma unroll
        for (int c = 0; c < DI; c++) acc[c] = 0.f;
        if (hp >= 0) {
            const float* fp = g_f + ((size_t)b * LS + hp) * DM;
            float xh[DM]; float s = 0.f;
#pragma unroll
            for (int d = 0; d < DM; d++) { float v = fp[d]; xh[d] = v; s += v * v; }
            float inv = rsqrtf(s * (1.0f / DM) + 1e-5f);
#pragma unroll
            for (int d = 0; d < DM; d++) xh[d] *= inv * s_norm[d];
#pragma unroll
            for (int c = 0; c < DI; c++) {
                float a = 0.f;
#pragma unroll
                for (int d = 0; d < DM; d++) a += s_inw[c * DM + d] * xh[d];
                acc[c] = a;
            }
        }
#pragma unroll
        for (int c = 0; c < DI; c++) s_xc[tid][c] = acc[c];
    }
    __syncthreads();
    if (!valid) return;

    float uu[DI];
#pragma unroll
    for (int c = 0; c < DI; c++) {
        float a = s_cb[c] + s_cw[c * 3 + 0] * s_xc[tid][c]
                          + s_cw[c * 3 + 1] * s_xc[tid + 1][c]
                          + s_cw[c * 3 + 2] * s_xc[tid + 2][c];
        uu[c] = a / (1.f + __expf(-a));            // silu
    }
    float* up = g_u + ((size_t)b * LS + pos) * DI;
#pragma unroll
    for (int c = 0; c < DI; c++) up[c] = uu[c];

    float dr = 0.f;
#pragma unroll
    for (int c = 0; c < DI; c++) dr += s_xw[c] * uu[c];

    float2* bcp = g_bc + ((size_t)b * LS + pos) * DS;
#pragma unroll
    for (int nn = 0; nn < DS; nn++) {
        float Bv = 0.f, Cv = 0.f;
#pragma unroll
        for (int c = 0; c < DI; c++) {
            Bv += s_xw[(1 + nn) * DI + c] * uu[c];
            Cv += s_xw[(1 + DS + nn) * DI + c] * uu[c];
        }
        bcp[nn] = make_float2(Bv, Cv);
    }
    float2* ddp = g_dd + ((size_t)b * LS + pos) * DI;
#pragma unroll
    for (int e = 0; e < DI; e++) {
        float t = dr * s_dtw[e] + s_dtb[e];
        float delta = (t > 20.f) ? t : log1pf(__expf(t));   // softplus
        ddp[e] = make_float2(delta, delta * uu[e]);
    }
}

// ---------------- selective scan: 1 block / batch, thread = (e,n) ----------------
__global__ void k_scan(const float* __restrict__ A_log) {
    int b = blockIdx.x;
    int tid = threadIdx.x;
    int e = tid >> 4, n = tid & 15;
    float A = -__expf(A_log[e * DS + n]);
    const float2* pdd = g_dd + (size_t)b * LS * DI + e;
    const float2* pbc = g_bc + (size_t)b * LS * DS + n;
    float* py = g_y + (size_t)b * LS * DI + e;

    float h = 0.f;
    float2 d2 = pdd[0];
    float2 cc = pbc[0];
#pragma unroll 4
    for (int t = 0; t < LS; t++) {
        float2 d2c = d2, ccc = cc;
        if (t + 1 < LS) {                     // prefetch next step (off critical path)
            d2 = pdd[(size_t)(t + 1) * DI];
            cc = pbc[(size_t)(t + 1) * DS];
        }
        float dA = __expf(d2c.x * A);
        h = __fmaf_rn(dA, h, d2c.y * ccc.x);  // h = exp(dt*A)*h + dt*u*B
        float v = h * ccc.y;
        v += __shfl_xor_sync(0xffffffffu, v, 1);
        v += __shfl_xor_sync(0xffffffffu, v, 2);
        v += __shfl_xor_sync(0xffffffffu, v, 4);
        v += __shfl_xor_sync(0xffffffffu, v, 8);
        if (n == 0) py[(size_t)t * DI] = v;
    }
}

// ---------------- phase C: f += out_proj @ ((y + D*u)*silu(z)) ----------------
__global__ void k_mix(const float* __restrict__ ow, const float* __restrict__ Dp) {
    __shared__ float s_w[DM * DI];
    __shared__ float s_D[DI];
    int tid = threadIdx.x;
    if (tid < DM * DI) s_w[tid] = ow[tid];
    if (tid < DI) s_D[tid] = Dp[tid];
    __syncthreads();
    int id = blockIdx.x * blockDim.x + tid;
    if (id >= BB * LS) return;
    const float* yp = g_y + (size_t)id * DI;
    const float* up = g_u + (size_t)id * DI;
    const float* zp = g_z + (size_t)id * DI;
    float g[DI];
#pragma unroll
    for (int c = 0; c < DI; c++) {
        float yv = yp[c] + s_D[c] * up[c];
        float zz = zp[c];
        g[c] = yv * (zz / (1.f + __expf(-zz)));
    }
    float* fp = g_f + (size_t)id * DM;
#pragma unroll
    for (int d = 0; d < DM; d++) {
        float a = 0.f;
#pragma unroll
        for (int c = 0; c < DI; c++) a += s_w[d * DI + c] * g[c];
        fp[d] += a;
    }
}

// ---------------- conv1: 8 -> 64, k=3, pad same, relu ----------------
#define LT1 128
__global__ void k_conv1(const float* __restrict__ w, const float* __restrict__ bias) {
    __shared__ float s_in[DM][LT1 + 2];
    __shared__ float s_w[HIDC * DM * 3];
    __shared__ float s_b[HIDC];
    int tid = threadIdx.x;                    // 256
    int b = blockIdx.y;
    int l0 = blockIdx.x * LT1;
    for (int i = tid; i < HIDC * DM * 3; i += 256) s_w[i] = w[i];
    if (tid < HIDC) s_b[tid] = bias[tid];
    for (int i = tid; i < DM * (LT1 + 2); i += 256) {
        int li = i / DM, d = i % DM;
        int l = l0 - 1 + li;
        s_in[d][li] = (l >= 0 && l < LS) ? g_f[((size_t)b * LS + l) * DM + d] : 0.f;
    }
    __syncthreads();
    int c = tid & 63, pg = tid >> 6;          // 4 groups x 32 positions
    float wr[24];
#pragma unroll
    for (int j = 0; j < 24; j++) wr[j] = s_w[c * 24 + j];
    float bb = s_b[c];
    int pbase = pg * 32;
    for (int j0 = 0; j0 < 32; j0 += 4) {
        int p = pbase + j0;
        float a0 = bb, a1 = bb, a2 = bb, a3 = bb;
#pragma unroll
        for (int d = 0; d < DM; d++) {
            float x0 = s_in[d][p + 0], x1 = s_in[d][p + 1], x2 = s_in[d][p + 2];
            float x3 = s_in[d][p + 3], x4 = s_in[d][p + 4], x5 = s_in[d][p + 5];
            float w0 = wr[d * 3 + 0], w1 = wr[d * 3 + 1], w2 = wr[d * 3 + 2];
            a0 += w0 * x0 + w1 * x1 + w2 * x2;
            a1 += w0 * x1 + w1 * x2 + w2 * x3;
            a2 += w0 * x2 + w1 * x3 + w2 * x4;
            a3 += w0 * x3 + w1 * x4 + w2 * x5;
        }
        int l = l0 + p;
        float* op = g_h1 + ((size_t)b * HIDC + c) * LS + l;
        if (l + 3 < LS) {
            *(float4*)op = make_float4(fmaxf(a0, 0.f), fmaxf(a1, 0.f),
                                       fmaxf(a2, 0.f), fmaxf(a3, 0.f));
        } else {
            if (l + 0 < LS) op[0] = fmaxf(a0, 0.f);
            if (l + 1 < LS) op[1] = fmaxf(a1, 0.f);
            if (l + 2 < LS) op[2] = fmaxf(a2, 0.f);
            if (l + 3 < LS) op[3] = fmaxf(a3, 0.f);
        }
    }
}

// ---------------- conv2: 64 -> 64, k=3, relu ----------------
#define LT2 64
__global__ void k_conv2(const float* __restrict__ w, const float* __restrict__ bias) {
    __shared__ float s_in[HIDC][LT2 + 2];     // 16.9 KB
    __shared__ float s_w[192 * 32];           // transposed: [(ci*3+k)*32 + c_local]
    __shared__ float s_b[32];
    int tid = threadIdx.x;                    // 256
    int b = blockIdx.y;
    int l0 = blockIdx.x * LT2;
    int ch = blockIdx.z;                      // c_out half
    for (int i = tid; i < HIDC * (LT2 + 2); i += 256) {
        int ci = i / (LT2 + 2), li = i % (LT2 + 2);
        int l = l0 - 1 + li;
        s_in[ci][li] = (l >= 0 && l < LS) ? g_h1[((size_t)b * HIDC + ci) * LS + l] : 0.f;
    }
    for (int i = tid; i < 32 * 192; i += 256) {
        int cl = i / 192, rem = i % 192;
        s_w[rem * 32 + cl] = w[(size_t)(ch * 32 + cl) * 192 + rem];
    }
    if (tid < 32) s_b[tid] = bias[ch * 32 + tid];
    __syncthreads();

    int c = tid & 31, pg = tid >> 5;          // 8 groups x 8 positions
    int p0 = pg * 8;
    float acc[8];
    float bb = s_b[c];
#pragma unroll
    for (int j = 0; j < 8; j++) acc[j] = bb;
    for (int ci = 0; ci < HIDC; ci++) {
        float w0 = s_w[(ci * 3 + 0) * 32 + c];
        float w1 = s_w[(ci * 3 + 1) * 32 + c];
        float w2 = s_w[(ci * 3 + 2) * 32 + c];
        float x[10];
#pragma unroll
        for (int j = 0; j < 10; j++) x[j] = s_in[ci][p0 + j];
#pragma unroll
        for (int j = 0; j < 8; j++) acc[j] += w0 * x[j] + w1 * x[j + 1] + w2 * x[j + 2];
    }
    int cg = ch * 32 + c;
    int l = l0 + p0;
    float* op = g_r + ((size_t)b * HIDC + cg) * LS + l;
#pragma unroll
    for (int j = 0; j < 8; j += 4) {
        if (l + j + 3 < LS) {
            *(float4*)(op + j) = make_float4(fmaxf(acc[j], 0.f), fmaxf(acc[j + 1], 0.f),
                                             fmaxf(acc[j + 2], 0.f), fmaxf(acc[j + 3], 0.f));
        } else {
#pragma unroll
            for (int jj = 0; jj < 4; jj++)
                if (l + j + jj < LS) op[j + jj] = fmaxf(acc[j + jj], 0.f);
        }
    }
}

// ---------------- conv3 + residual + relu + mean-pool partial ----------------
#define LT3 48
__global__ void k_conv3(const float* __restrict__ w, const float* __restrict__ bias) {
    __shared__ float s_in[HIDC][LT3 + 2];     // 12.8 KB (r tile)
    __shared__ float s_w[192 * 32];           // 24.6 KB
    __shared__ float s_h[32][LT3 + 1];        // 6.3 KB (h1 tile, padded)
    __shared__ float s_b[32];
    __shared__ float s_red[8][33];
    int tid = threadIdx.x;                    // 256
    int b = blockIdx.y;
    int l0 = blockIdx.x * LT3;
    int ch = blockIdx.z;
    for (int i = tid; i < HIDC * (LT3 + 2); i += 256) {
        int ci = i / (LT3 + 2), li = i % (LT3 + 2);
        int l = l0 - 1 + li;
        s_in[ci][li] = (l >= 0 && l < LS) ? g_r[((size_t)b * HIDC + ci) * LS + l] : 0.f;
    }
    for (int i = tid; i < 32 * 192; i += 256) {
        int cl = i / 192, rem = i % 192;
        s_w[rem * 32 + cl] = w[(size_t)(ch * 32 + cl) * 192 + rem];
    }
    for (int i = tid; i < 32 * LT3; i += 256) {
        int cl = i / LT3, li = i % LT3;
        int l = l0 + li;
        s_h[cl][li] = (l < LS) ? g_h1[((size_t)b * HIDC + ch * 32 + cl) * LS + l] : 0.f;
    }
    if (tid < 32) s_b[tid] = bias[ch * 32 + tid];
    __syncthreads();

    int c = tid & 31, pg = tid >> 5;          // 8 groups x 6 positions
    int p0 = pg * 6;
    float acc[6];
    float bb = s_b[c];
#pragma unroll
    for (int j = 0; j < 6; j++) acc[j] = bb;
    for (int ci = 0; ci < HIDC; ci++) {
        float w0 = s_w[(ci * 3 + 0) * 32 + c];
        float w1 = s_w[(ci * 3 + 1) * 32 + c];
        float w2 = s_w[(ci * 3 + 2) * 32 + c];
        float x[8];
#pragma unroll
        for (int j = 0; j < 8; j++) x[j] = s_in[ci][p0 + j];
#pragma unroll
        for (int j = 0; j < 6; j++) acc[j] += w0 * x[j] + w1 * x[j + 1] + w2 * x[j + 2];
    }
    float psum = 0.f;
    int l = l0 + p0;
#pragma unroll
    for (int j = 0; j < 6; j++) {
        if (l + j < LS) {
            float t = acc[j] + s_h[c][p0 + j];    // h1 + conv3(r)
            psum += fmaxf(t, 0.f);
        }
    }
    s_red[pg][c] = psum;
    __syncthreads();
    if (tid < 32) {
        float s = 0.f;
#pragma unroll
        for (int g = 0; g < 8; g++) s += s_red[g][tid];
        atomicAdd(&g_pool[b * HIDC + ch * 32 + tid], s);
    }
}

// ---------------- fc ----------------
__global__ void k_fc(const float* __restrict__ fw, const float* __restrict__ fb,
                     float* __restrict__ out) {
    __shared__ float s_p[HIDC];
    int b = blockIdx.x, tid = threadIdx.x;
    if (tid < HIDC) s_p[tid] = g_pool[b * HIDC + tid] * (1.0f / LS);
    __syncthreads();
    if (tid < NC) {
        float a = fb[tid];
#pragma unroll
        for (int c = 0; c < HIDC; c++) a += fw[tid * HIDC + c] * s_p[c];
        out[b * NC + tid] = a;
    }
}

// ---------------- launch ----------------
extern "C" void kernel_launch(void* const* d_in, const int* in_sizes, int n_in,
                              void* d_out, int out_size) {
    const float* x          = (const float*)d_in[0];
    const int*   idx        = (const int*)  d_in[1];
    const float* emb        = (const float*)d_in[2];
    const float* norm_w     = (const float*)d_in[3];
    const float* in_proj_w  = (const float*)d_in[4];
    const float* conv_w     = (const float*)d_in[5];
    const float* conv_b     = (const float*)d_in[6];
    const float* x_proj_w   = (const float*)d_in[7];
    const float* dt_proj_w  = (const float*)d_in[8];
    const float* dt_proj_b  = (const float*)d_in[9];
    const float* A_log      = (const float*)d_in[10];
    const float* Dp         = (const float*)d_in[11];
    const float* out_proj_w = (const float*)d_in[12];
    const float* c1w        = (const float*)d_in[13];
    const float* c1b        = (const float*)d_in[14];
    const float* c2w        = (const float*)d_in[15];
    const float* c2b        = (const float*)d_in[16];
    const float* c3w        = (const float*)d_in[17];
    const float* c3b        = (const float*)d_in[18];
    const float* fcw        = (const float*)d_in[19];
    const float* fcb        = (const float*)d_in[20];
    float* out = (float*)d_out;

    k_embed<<<(BB * LS + 255) / 256, 256>>>(x, idx, emb);
    k_zero<<<(BB * HIDC + 255) / 256, 256>>>();

    for (int l = 0; l < NL; l++) {
        k_layerA<<<dim3((LS + LTA - 1) / LTA, BB), LTA>>>(
            norm_w + l * DM, in_proj_w + l * 32 * DM, conv_w + l * DI * 3,
            conv_b + l * DI, x_proj_w + l * 33 * DI, dt_proj_w + l * DI,
            dt_proj_b + l * DI);
        k_scan<<<BB, 256>>>(A_log + l * DI * DS);
        k_mix<<<(BB * LS + 255) / 256, 256>>>(out_proj_w + l * DM * DI, Dp + l * DI);
    }

    k_conv1<<<dim3((LS + LT1 - 1) / LT1, BB), 256>>>(c1w, c1b);
    k_conv2<<<dim3((LS + LT2 - 1) / LT2, BB, 2), 256>>>(c2w, c2b);
    k_conv3<<<dim3((LS + LT3 - 1) / LT3, BB, 2), 256>>>(c3w, c3b);
    k_fc<<<BB, 256>>>(fcw, fcb, out);
}